// round 15
// baseline (speedup 1.0000x reference)
#include <cuda_runtime.h>
#include <cuda_fp16.h>
#include <cstdint>

#define NN 8192
#define NE 262144
#define FIN 512
#define H1D 256
#define H2D 128
#define H3D 64
#define O6 6

// ---------------- device scratch ----------------
__device__ __half g_xw1h[NN * H1D];   // xw1 in fp16
__device__ __half g_h1h[NN * H1D];    // h1 in fp16
__device__ float  g_ah1[NN * H1D];    // ah1 fp32 (feeds ml)
__device__ float  g_Wcat[H1D * H2D];
__device__ int    g_cnt[NN];          // zero-init; invariant: returns to 0 after scatter
__device__ int    g_rp[NN + 1];
__device__ int2   g_colval[NE];
// fp16 fragment packs
__device__ uint4 g_XAh[512 * 32 * 32];
__device__ uint4 g_XAl[512 * 32 * 32];
__device__ uint2 g_WBh[32 * 32 * 32];
__device__ uint4 g_MAh[512 * 4 * 32];
__device__ uint2 g_MBh[1024 * 4 * 32];

// ---------------- fp16 helpers ----------------
__device__ __forceinline__ void hsplit2(float x0, float x1, unsigned& hp, unsigned& lp) {
    __half h0 = __float2half_rn(x0), h1 = __float2half_rn(x1);
    float r0 = x0 - __half2float(h0), r1 = x1 - __half2float(h1);
    __half l0 = __float2half_rn(r0), l1 = __float2half_rn(r1);
    hp = (unsigned)__half_as_ushort(h0) | ((unsigned)__half_as_ushort(h1) << 16);
    lp = (unsigned)__half_as_ushort(l0) | ((unsigned)__half_as_ushort(l1) << 16);
}
__device__ __forceinline__ unsigned hpack2(float x0, float x1) {
    __half h0 = __float2half_rn(x0), h1 = __float2half_rn(x1);
    return (unsigned)__half_as_ushort(h0) | ((unsigned)__half_as_ushort(h1) << 16);
}

__device__ __forceinline__ void mma_u4(float* c, const uint4& a, const uint2& b) {
    asm volatile(
        "mma.sync.aligned.m16n8k16.row.col.f32.f16.f16.f32 "
        "{%0,%1,%2,%3}, {%4,%5,%6,%7}, {%8,%9}, {%0,%1,%2,%3};"
        : "+f"(c[0]), "+f"(c[1]), "+f"(c[2]), "+f"(c[3])
        : "r"(a.x), "r"(a.y), "r"(a.z), "r"(a.w), "r"(b.x), "r"(b.y));
}

// ================= pack x (blocks 0..511) + W1 (blocks 512..543) =================
__global__ void pack_inputs_kernel(const float* __restrict__ x, const float* __restrict__ W1) {
    int lane = threadIdx.x & 31, ks = threadIdx.x >> 5;
    int lr = lane >> 2, lc = lane & 3;
    if (blockIdx.x < 512) {
        int g = blockIdx.x;
        int row0 = g * 16 + lr, k0 = ks * 16, c0 = k0 + 2 * lc;
        float2 v0 = *(const float2*)&x[(size_t)row0 * FIN + c0];
        float2 v1 = *(const float2*)&x[(size_t)(row0 + 8) * FIN + c0];
        float2 v2 = *(const float2*)&x[(size_t)row0 * FIN + c0 + 8];
        float2 v3 = *(const float2*)&x[(size_t)(row0 + 8) * FIN + c0 + 8];
        uint4 h, l;
        hsplit2(v0.x, v0.y, h.x, l.x);
        hsplit2(v1.x, v1.y, h.y, l.y);
        hsplit2(v2.x, v2.y, h.z, l.z);
        hsplit2(v3.x, v3.y, h.w, l.w);
        int idx = (g * 32 + ks) * 32 + lane;
        g_XAh[idx] = h;
        g_XAl[idx] = l;
    } else {
        int gb = blockIdx.x - 512;
        int n0 = gb * 8 + lr, k0 = ks * 16, kc = k0 + 2 * lc;
        float b00 = W1[(size_t)kc * H1D + n0];
        float b01 = W1[(size_t)(kc + 1) * H1D + n0];
        float b10 = W1[(size_t)(kc + 8) * H1D + n0];
        float b11 = W1[(size_t)(kc + 9) * H1D + n0];
        uint2 h;
        h.x = hpack2(b00, b01);
        h.y = hpack2(b10, b11);
        int idx = (gb * 32 + ks) * 32 + lane;
        g_WBh[idx] = h;
    }
}

// ================= xw1: 128x128 tiles, 2-term fp16, double-buffered frag prefetch =========
__global__ void __launch_bounds__(256) xw1_mma_kernel(__half* __restrict__ C) {
    int tid = threadIdx.x;
    int lane = tid & 31, warp = tid >> 5;
    int wr = warp >> 2, wc = warp & 3;
    int lr = lane >> 2, lc = lane & 3;
    int ga0 = blockIdx.y * 8 + wr * 4;
    int gb0 = blockIdx.x * 16 + wc * 4;

    float acc[4][4][4];
#pragma unroll
    for (int m = 0; m < 4; m++)
#pragma unroll
        for (int n = 0; n < 4; n++)
#pragma unroll
            for (int q = 0; q < 4; q++) acc[m][n][q] = 0.f;

    uint4 ah[2][4], al[2][4];
    uint2 bh[2][4];
#pragma unroll
    for (int mf = 0; mf < 4; mf++) {
        int ia = ((ga0 + mf) * 32) * 32 + lane;
        ah[0][mf] = g_XAh[ia];
        al[0][mf] = g_XAl[ia];
    }
#pragma unroll
    for (int nf = 0; nf < 4; nf++) {
        int ib = ((gb0 + nf) * 32) * 32 + lane;
        bh[0][nf] = g_WBh[ib];
    }

#pragma unroll 2
    for (int ks = 0; ks < 32; ks++) {
        int cur = ks & 1, nxt = cur ^ 1;
        if (ks < 31) {
#pragma unroll
            for (int mf = 0; mf < 4; mf++) {
                int ia = ((ga0 + mf) * 32 + ks + 1) * 32 + lane;
                ah[nxt][mf] = g_XAh[ia];
                al[nxt][mf] = g_XAl[ia];
            }
#pragma unroll
            for (int nf = 0; nf < 4; nf++) {
                int ib = ((gb0 + nf) * 32 + ks + 1) * 32 + lane;
                bh[nxt][nf] = g_WBh[ib];
            }
        }
#pragma unroll
        for (int mf = 0; mf < 4; mf++)
#pragma unroll
            for (int nf = 0; nf < 4; nf++) mma_u4(acc[mf][nf], ah[cur][mf], bh[cur][nf]);
#pragma unroll
        for (int mf = 0; mf < 4; mf++)
#pragma unroll
            for (int nf = 0; nf < 4; nf++) mma_u4(acc[mf][nf], al[cur][mf], bh[cur][nf]);
    }
#pragma unroll
    for (int mf = 0; mf < 4; mf++) {
        int r = blockIdx.y * 128 + wr * 64 + mf * 16 + lr;
#pragma unroll
        for (int nf = 0; nf < 4; nf++) {
            int j = blockIdx.x * 128 + wc * 32 + nf * 8 + 2 * lc;
            *(__half2*)&C[(size_t)r * H1D + j] =
                __floats2half2_rn(acc[mf][nf][0], acc[mf][nf][1]);
            *(__half2*)&C[(size_t)(r + 8) * H1D + j] =
                __floats2half2_rn(acc[mf][nf][2], acc[mf][nf][3]);
        }
    }
}

// ================= CSR build =================
__global__ void hist_kernel(const int* __restrict__ rows) {
    int i = blockIdx.x * 256 + threadIdx.x;
    int4 r = ((const int4*)rows)[i];
    atomicAdd(&g_cnt[r.x], 1);
    atomicAdd(&g_cnt[r.y], 1);
    atomicAdd(&g_cnt[r.z], 1);
    atomicAdd(&g_cnt[r.w], 1);
}

__global__ void scan_kernel() {
    __shared__ int wtot[32];
    __shared__ int wexc[32];
    int t = threadIdx.x;
    int lane = t & 31, warp = t >> 5;
    int4 a = ((const int4*)g_cnt)[t * 2];
    int4 b = ((const int4*)g_cnt)[t * 2 + 1];
    int s8 = a.x + a.y + a.z + a.w + b.x + b.y + b.z + b.w;
    int inc = s8;
#pragma unroll
    for (int d = 1; d < 32; d <<= 1) {
        int v = __shfl_up_sync(0xffffffff, inc, d);
        if (lane >= d) inc += v;
    }
    if (lane == 31) wtot[warp] = inc;
    __syncthreads();
    if (warp == 0) {
        int v = wtot[lane];
        int wi = v;
#pragma unroll
        for (int d = 1; d < 32; d <<= 1) {
            int u = __shfl_up_sync(0xffffffff, wi, d);
            if (lane >= d) wi += u;
        }
        wexc[lane] = wi - v;
        if (lane == 31) g_rp[NN] = wi;
    }
    __syncthreads();
    int base = wexc[warp] + inc - s8;
    int o = base;
    g_rp[t * 8 + 0] = o; o += a.x;
    g_rp[t * 8 + 1] = o; o += a.y;
    g_rp[t * 8 + 2] = o; o += a.z;
    g_rp[t * 8 + 3] = o; o += a.w;
    g_rp[t * 8 + 4] = o; o += b.x;
    g_rp[t * 8 + 5] = o; o += b.y;
    g_rp[t * 8 + 6] = o; o += b.z;
    g_rp[t * 8 + 7] = o;
}

__global__ void scatter_kernel(const int* __restrict__ rows, const int* __restrict__ cols,
                               const float* __restrict__ vals) {
    int e = blockIdx.x * 256 + threadIdx.x;
    int r = rows[e];
    int old = atomicSub(&g_cnt[r], 1);
    int pos = g_rp[r] + old - 1;
    g_colval[pos] = make_int2(cols[e], __float_as_int(vals[e]));
}

// ================= SpMM (half in, half out + relu) =================
__global__ void spmm_h2h(const __half* __restrict__ X, __half* __restrict__ Y) {
    int r = blockIdx.x * 4 + (threadIdx.x >> 6);
    int t = threadIdx.x & 63;
    int s = g_rp[r], e = g_rp[r + 1];
    const uint2* Xu = (const uint2*)X;
    float4 acc = make_float4(0.f, 0.f, 0.f, 0.f);
    int i = s;
    for (; i + 4 <= e; i += 4) {
        int2 c0 = g_colval[i], c1 = g_colval[i + 1], c2 = g_colval[i + 2], c3 = g_colval[i + 3];
        uint2 r0 = Xu[(size_t)c0.x * 64 + t];
        uint2 r1 = Xu[(size_t)c1.x * 64 + t];
        uint2 r2 = Xu[(size_t)c2.x * 64 + t];
        uint2 r3 = Xu[(size_t)c3.x * 64 + t];
        float v0 = __int_as_float(c0.y), v1 = __int_as_float(c1.y);
        float v2 = __int_as_float(c2.y), v3 = __int_as_float(c3.y);
        float2 a0 = __half22float2(*(__half2*)&r0.x), b0 = __half22float2(*(__half2*)&r0.y);
        float2 a1 = __half22float2(*(__half2*)&r1.x), b1 = __half22float2(*(__half2*)&r1.y);
        float2 a2 = __half22float2(*(__half2*)&r2.x), b2 = __half22float2(*(__half2*)&r2.y);
        float2 a3 = __half22float2(*(__half2*)&r3.x), b3 = __half22float2(*(__half2*)&r3.y);
        acc.x += v0 * a0.x + v1 * a1.x + v2 * a2.x + v3 * a3.x;
        acc.y += v0 * a0.y + v1 * a1.y + v2 * a2.y + v3 * a3.y;
        acc.z += v0 * b0.x + v1 * b1.x + v2 * b2.x + v3 * b3.x;
        acc.w += v0 * b0.y + v1 * b1.y + v2 * b2.y + v3 * b3.y;
    }
    for (; i < e; i++) {
        int2 c = g_colval[i];
        uint2 rv = Xu[(size_t)c.x * 64 + t];
        float v = __int_as_float(c.y);
        float2 a = __half22float2(*(__half2*)&rv.x), b = __half22float2(*(__half2*)&rv.y);
        acc.x += v * a.x; acc.y += v * a.y; acc.z += v * b.x; acc.w += v * b.y;
    }
    uint2 out;
    __half2 o0 = __floats2half2_rn(fmaxf(acc.x, 0.f), fmaxf(acc.y, 0.f));
    __half2 o1 = __floats2half2_rn(fmaxf(acc.z, 0.f), fmaxf(acc.w, 0.f));
    out.x = *(unsigned*)&o0;
    out.y = *(unsigned*)&o1;
    ((uint2*)Y)[(size_t)r * 64 + t] = out;
}

// ================= SpMM (half in, float out, no relu) =================
__global__ void spmm_h2f(const __half* __restrict__ X, float* __restrict__ Y) {
    int r = blockIdx.x * 4 + (threadIdx.x >> 6);
    int t = threadIdx.x & 63;
    int s = g_rp[r], e = g_rp[r + 1];
    const uint2* Xu = (const uint2*)X;
    float4 acc = make_float4(0.f, 0.f, 0.f, 0.f);
    int i = s;
    for (; i + 4 <= e; i += 4) {
        int2 c0 = g_colval[i], c1 = g_colval[i + 1], c2 = g_colval[i + 2], c3 = g_colval[i + 3];
        uint2 r0 = Xu[(size_t)c0.x * 64 + t];
        uint2 r1 = Xu[(size_t)c1.x * 64 + t];
        uint2 r2 = Xu[(size_t)c2.x * 64 + t];
        uint2 r3 = Xu[(size_t)c3.x * 64 + t];
        float v0 = __int_as_float(c0.y), v1 = __int_as_float(c1.y);
        float v2 = __int_as_float(c2.y), v3 = __int_as_float(c3.y);
        float2 a0 = __half22float2(*(__half2*)&r0.x), b0 = __half22float2(*(__half2*)&r0.y);
        float2 a1 = __half22float2(*(__half2*)&r1.x), b1 = __half22float2(*(__half2*)&r1.y);
        float2 a2 = __half22float2(*(__half2*)&r2.x), b2 = __half22float2(*(__half2*)&r2.y);
        float2 a3 = __half22float2(*(__half2*)&r3.x), b3 = __half22float2(*(__half2*)&r3.y);
        acc.x += v0 * a0.x + v1 * a1.x + v2 * a2.x + v3 * a3.x;
        acc.y += v0 * a0.y + v1 * a1.y + v2 * a2.y + v3 * a3.y;
        acc.z += v0 * b0.x + v1 * b1.x + v2 * b2.x + v3 * b3.x;
        acc.w += v0 * b0.y + v1 * b1.y + v2 * b2.y + v3 * b3.y;
    }
    for (; i < e; i++) {
        int2 c = g_colval[i];
        uint2 rv = Xu[(size_t)c.x * 64 + t];
        float v = __int_as_float(c.y);
        float2 a = __half22float2(*(__half2*)&rv.x), b = __half22float2(*(__half2*)&rv.y);
        acc.x += v * a.x; acc.y += v * a.y; acc.z += v * b.x; acc.w += v * b.y;
    }
    ((float4*)Y)[(size_t)r * 64 + t] = acc;
}

// ================= Wcat = [W2@dense_W | W3@dense_W] =================
__global__ void wcat_kernel(const float* __restrict__ W2, const float* __restrict__ W3,
                            const float* __restrict__ dW) {
    int k = blockIdx.x;
    int c = threadIdx.x;
    const float* Ws = (c < 64) ? W2 : W3;
    int cc = c & 63;
    float a = 0.f;
#pragma unroll 4
    for (int j = 0; j < H2D; j++) a += Ws[k * H2D + j] * dW[j * H3D + cc];
    g_Wcat[k * H2D + c] = a;
}

// ========== fused: mu/lv = ah1@Wcat + bias, + mu frag packs + o6, one kernel ==========
__global__ void __launch_bounds__(256) ml_fused_kernel(
    const float* __restrict__ A, const float* __restrict__ db,
    const float* __restrict__ d1W, const float* __restrict__ d1b,
    float* __restrict__ mu, float* __restrict__ lv, float* __restrict__ o6) {
    const int BK = 16;
    __shared__ float As[BK][132];
    __shared__ float Bs[BK][132];
    __shared__ unsigned muS[128][34];   // packed half2 pairs of mu (cols 0..63 -> 32 pairs)
    __shared__ float w6[64 * O6];
    __shared__ float b6[O6];
    int tid = threadIdx.x;
    for (int i = tid; i < 64 * O6; i += 256) w6[i] = d1W[i];   // FIX: strided (384 > 256)
    if (tid < O6) b6[tid] = d1b[tid];
    int tx = tid & 15, ty = tid >> 4;
    int row0 = blockIdx.x * 128;
    float acc[8][8];
#pragma unroll
    for (int r = 0; r < 8; r++)
#pragma unroll
        for (int c = 0; c < 8; c++) acc[r][c] = 0.f;
    for (int k0 = 0; k0 < H1D; k0 += BK) {
#pragma unroll
        for (int i = 0; i < 2; i++) {
            int idx = tid + i * 256;
            int ar = idx >> 2, kq = (idx & 3) * 4;
            float4 v = *(const float4*)&A[(size_t)(row0 + ar) * H1D + k0 + kq];
            As[kq + 0][ar] = v.x; As[kq + 1][ar] = v.y;
            As[kq + 2][ar] = v.z; As[kq + 3][ar] = v.w;
        }
        {
            int br = tid >> 5, bc = (tid & 31) * 4;
            *(float4*)&Bs[br][bc] = *(const float4*)&g_Wcat[(k0 + br) * H2D + bc];
            *(float4*)&Bs[br + 8][bc] = *(const float4*)&g_Wcat[(k0 + br + 8) * H2D + bc];
        }
        __syncthreads();
#pragma unroll
        for (int kk = 0; kk < BK; kk++) {
            float a[8], b[8];
            *(float4*)&a[0] = *(float4*)&As[kk][ty * 8];
            *(float4*)&a[4] = *(float4*)&As[kk][ty * 8 + 4];
            *(float4*)&b[0] = *(float4*)&Bs[kk][tx * 8];
            *(float4*)&b[4] = *(float4*)&Bs[kk][tx * 8 + 4];
#pragma unroll
            for (int r = 0; r < 8; r++)
#pragma unroll
                for (int c = 0; c < 8; c++) acc[r][c] += a[r] * b[c];
        }
        __syncthreads();
    }
    int colg = tx * 8;
    float bias[8];
#pragma unroll
    for (int c = 0; c < 8; c++) bias[c] = __ldg(&db[(colg + c) & 63]);
    int cc = colg & 63;
    float* dst = (colg < 64) ? mu : lv;
#pragma unroll
    for (int r = 0; r < 8; r++) {
        int rl = ty * 8 + r;
        int rg = row0 + rl;
        float v[8];
#pragma unroll
        for (int c = 0; c < 8; c++) v[c] = acc[r][c] + bias[c];
        *(float4*)&dst[(size_t)rg * 64 + cc] = make_float4(v[0], v[1], v[2], v[3]);
        *(float4*)&dst[(size_t)rg * 64 + cc + 4] = make_float4(v[4], v[5], v[6], v[7]);
        if (colg < 64) {
#pragma unroll
            for (int q = 0; q < 4; q++)
                muS[rl][(colg >> 1) + q] = hpack2(v[2 * q], v[2 * q + 1]);
        }
    }
    __syncthreads();
    // A-frag pack: 8 groups x 4 ks x 32 lanes
    for (int i = tid; i < 1024; i += 256) {
        int gl = i >> 7, ks = (i >> 5) & 3, lane = i & 31;
        int lr = lane >> 2, lc = lane & 3;
        int rl = gl * 16 + lr;
        int ci = ks * 8 + lc;
        uint4 h;
        h.x = muS[rl][ci];
        h.y = muS[rl + 8][ci];
        h.z = muS[rl][ci + 4];
        h.w = muS[rl + 8][ci + 4];
        g_MAh[((row0 / 16 + gl) * 4 + ks) * 32 + lane] = h;
    }
    // B-frag pack: 16 groups x 4 ks x 32 lanes
    for (int i = tid; i < 2048; i += 256) {
        int gl = i >> 7, ks = (i >> 5) & 3, lane = i & 31;
        int lr = lane >> 2, lc = lane & 3;
        int nl = gl * 8 + lr;
        int ci = ks * 8 + lc;
        uint2 h;
        h.x = muS[nl][ci];
        h.y = muS[nl][ci + 4];
        g_MBh[((row0 / 8 + gl) * 4 + ks) * 32 + lane] = h;
    }
    // o6: 128 rows x 6 cols
    for (int i = tid; i < 128 * O6; i += 256) {
        int rl = i / O6, c = i - rl * O6;
        float a = b6[c];
#pragma unroll 8
        for (int k = 0; k < 32; k++) {
            unsigned p = muS[rl][k];
            float2 f = __half22float2(*(__half2*)&p);
            a += f.x * w6[(2 * k) * O6 + c] + f.y * w6[(2 * k + 1) * O6 + c];
        }
        o6[(size_t)(row0 + rl) * O6 + c] = a;
    }
}

// ================= zzt: 128 threads, warp tile 64x64, mirror, 1-term fp16 ==========
__global__ void __launch_bounds__(128) zzt_kernel(float* __restrict__ C) {
    int bx = blockIdx.x, by = blockIdx.y;
    if (by > bx) return;
    __shared__ float T[32][132];
    int tid = threadIdx.x;
    int lane = tid & 31, warp = tid >> 5;
    int wr = warp >> 1, wc = warp & 1;
    int lr = lane >> 2, lc = lane & 3;
    int i0 = by * 128, j0 = bx * 128;
    int ga0 = by * 8 + wr * 4;
    int gb0 = bx * 16 + wc * 8;

    float acc[4][8][4];
#pragma unroll
    for (int m = 0; m < 4; m++)
#pragma unroll
        for (int n = 0; n < 8; n++)
#pragma unroll
            for (int q = 0; q < 4; q++) acc[m][n][q] = 0.f;

#pragma unroll
    for (int ks = 0; ks < 4; ks++) {
        uint4 ah[4];
        uint2 bh[8];
#pragma unroll
        for (int mf = 0; mf < 4; mf++) {
            int ia = ((ga0 + mf) * 4 + ks) * 32 + lane;
            ah[mf] = g_MAh[ia];
        }
#pragma unroll
        for (int nf = 0; nf < 8; nf++) {
            int ib = ((gb0 + nf) * 4 + ks) * 32 + lane;
            bh[nf] = g_MBh[ib];
        }
#pragma unroll
        for (int mf = 0; mf < 4; mf++)
#pragma unroll
            for (int nf = 0; nf < 8; nf++) mma_u4(acc[mf][nf], ah[mf], bh[nf]);
    }
    // direct tile
#pragma unroll
    for (int mf = 0; mf < 4; mf++) {
        int r = i0 + wr * 64 + mf * 16 + lr;
#pragma unroll
        for (int nf = 0; nf < 8; nf++) {
            int j = j0 + wc * 64 + nf * 8 + 2 * lc;
            *(float2*)&C[(size_t)r * NN + j] = make_float2(acc[mf][nf][0], acc[mf][nf][1]);
            *(float2*)&C[(size_t)(r + 8) * NN + j] = make_float2(acc[mf][nf][2], acc[mf][nf][3]);
        }
    }
    if (bx == by) return;
    // mirror: 4 strips of 32 cols via smem transpose
#pragma unroll
    for (int s = 0; s < 4; s++) {
        __syncthreads();
        if (wc == (s >> 1)) {
            int nf0 = (s & 1) * 4;
#pragma unroll
            for (int mf = 0; mf < 4; mf++) {
                int rl = wr * 64 + mf * 16 + lr;
#pragma unroll
                for (int nf = 0; nf < 4; nf++) {
                    int cl = nf * 8 + 2 * lc;
                    T[cl][rl] = acc[mf][nf0 + nf][0];
                    T[cl + 1][rl] = acc[mf][nf0 + nf][1];
                    T[cl][rl + 8] = acc[mf][nf0 + nf][2];
                    T[cl + 1][rl + 8] = acc[mf][nf0 + nf][3];
                }
            }
        }
        __syncthreads();
        int jj = tid >> 2, seg = (tid & 3) * 32;
        size_t base = (size_t)(j0 + s * 32 + jj) * NN + i0 + seg;
#pragma unroll
        for (int q = 0; q < 8; q++)
            *(float4*)&C[base + q * 4] = *(float4*)&T[jj][seg + q * 4];
    }
}

// ================= launch =================
extern "C" void kernel_launch(void* const* d_in, const int* in_sizes, int n_in,
                              void* d_out, int out_size) {
    const float* x        = (const float*)d_in[0];
    const int*   adj_rows = (const int*)d_in[1];
    const int*   adj_cols = (const int*)d_in[2];
    const float* adj_vals = (const float*)d_in[3];
    const float* W1       = (const float*)d_in[4];
    const float* W2       = (const float*)d_in[5];
    const float* W3       = (const float*)d_in[6];
    const float* dense_W  = (const float*)d_in[7];
    const float* dense_b  = (const float*)d_in[8];
    const float* dense1_W = (const float*)d_in[9];
    const float* dense1_b = (const float*)d_in[10];

    float* out = (float*)d_out;
    float* adj = out;
    float* o6  = adj + (size_t)NN * NN;
    float* mu  = o6 + (size_t)NN * O6;
    float* lv  = mu + (size_t)NN * H3D;

    void *p_xw1h, *p_h1h, *p_ah1;
    cudaGetSymbolAddress(&p_xw1h, g_xw1h);
    cudaGetSymbolAddress(&p_h1h, g_h1h);
    cudaGetSymbolAddress(&p_ah1, g_ah1);

    // prep packs + small weights
    wcat_kernel<<<H1D, H2D>>>(W2, W3, dense_W);
    pack_inputs_kernel<<<544, 1024>>>(x, W1);

    // xw1 = x @ W1 (fp16 2-term, pipelined)
    xw1_mma_kernel<<<dim3(2, 64), 256>>>((__half*)p_xw1h);

    // CSR
    hist_kernel<<<NE / 1024, 256>>>(adj_rows);
    scan_kernel<<<1, 1024>>>();
    scatter_kernel<<<NE / 256, 256>>>(adj_rows, adj_cols, adj_vals);

    // SpMMs (half storage)
    spmm_h2h<<<NN / 4, 256>>>((const __half*)p_xw1h, (__half*)p_h1h);
    spmm_h2f<<<NN / 4, 256>>>((const __half*)p_h1h, (float*)p_ah1);

    // mu/lv + frag packs + o6, fused
    ml_fused_kernel<<<NN / 128, 256>>>((const float*)p_ah1, dense_b, dense1_W, dense1_b,
                                       mu, lv, o6);

    // adj_rec = mu @ mu^T (half grid + mirror, fp16 1-term)
    zzt_kernel<<<dim3(64, 64), 128>>>(adj);
}

// round 16
// speedup vs baseline: 1.4303x; 1.4303x over previous
#include <cuda_runtime.h>
#include <cuda_fp16.h>
#include <cstdint>

#define NN 8192
#define NE 262144
#define FIN 512
#define H1D 256
#define H2D 128
#define H3D 64
#define O6 6

// ---------------- device scratch ----------------
__device__ __half g_xw1h[NN * H1D];   // xw1 in fp16
__device__ __half g_h1h[NN * H1D];    // h1 in fp16
__device__ float  g_ah1[NN * H1D];    // ah1 fp32 (feeds ml)
__device__ float  g_Wcat[H1D * H2D];
__device__ int    g_cnt[NN];          // zero-init; invariant: returns to 0 after scatter
__device__ int    g_rp[NN + 1];
__device__ int2   g_colval[NE];
// fp16 fragment packs
__device__ uint4 g_XAh[512 * 32 * 32];
__device__ uint4 g_XAl[512 * 32 * 32];
__device__ uint2 g_WBh[32 * 32 * 32];
__device__ uint4 g_MAh[512 * 4 * 32];
__device__ uint2 g_MBh[1024 * 4 * 32];

// ---------------- fp16 helpers ----------------
__device__ __forceinline__ void hsplit2(float x0, float x1, unsigned& hp, unsigned& lp) {
    __half h0 = __float2half_rn(x0), h1 = __float2half_rn(x1);
    float r0 = x0 - __half2float(h0), r1 = x1 - __half2float(h1);
    __half l0 = __float2half_rn(r0), l1 = __float2half_rn(r1);
    hp = (unsigned)__half_as_ushort(h0) | ((unsigned)__half_as_ushort(h1) << 16);
    lp = (unsigned)__half_as_ushort(l0) | ((unsigned)__half_as_ushort(l1) << 16);
}
__device__ __forceinline__ unsigned hpack2(float x0, float x1) {
    __half h0 = __float2half_rn(x0), h1 = __float2half_rn(x1);
    return (unsigned)__half_as_ushort(h0) | ((unsigned)__half_as_ushort(h1) << 16);
}

__device__ __forceinline__ void mma_u4(float* c, const uint4& a, const uint2& b) {
    asm volatile(
        "mma.sync.aligned.m16n8k16.row.col.f32.f16.f16.f32 "
        "{%0,%1,%2,%3}, {%4,%5,%6,%7}, {%8,%9}, {%0,%1,%2,%3};"
        : "+f"(c[0]), "+f"(c[1]), "+f"(c[2]), "+f"(c[3])
        : "r"(a.x), "r"(a.y), "r"(a.z), "r"(a.w), "r"(b.x), "r"(b.y));
}

// ================= pack x (blocks 0..511) + W1 (blocks 512..543) =================
__global__ void pack_inputs_kernel(const float* __restrict__ x, const float* __restrict__ W1) {
    int lane = threadIdx.x & 31, ks = threadIdx.x >> 5;
    int lr = lane >> 2, lc = lane & 3;
    if (blockIdx.x < 512) {
        int g = blockIdx.x;
        int row0 = g * 16 + lr, k0 = ks * 16, c0 = k0 + 2 * lc;
        float2 v0 = *(const float2*)&x[(size_t)row0 * FIN + c0];
        float2 v1 = *(const float2*)&x[(size_t)(row0 + 8) * FIN + c0];
        float2 v2 = *(const float2*)&x[(size_t)row0 * FIN + c0 + 8];
        float2 v3 = *(const float2*)&x[(size_t)(row0 + 8) * FIN + c0 + 8];
        uint4 h, l;
        hsplit2(v0.x, v0.y, h.x, l.x);
        hsplit2(v1.x, v1.y, h.y, l.y);
        hsplit2(v2.x, v2.y, h.z, l.z);
        hsplit2(v3.x, v3.y, h.w, l.w);
        int idx = (g * 32 + ks) * 32 + lane;
        g_XAh[idx] = h;
        g_XAl[idx] = l;
    } else {
        int gb = blockIdx.x - 512;
        int n0 = gb * 8 + lr, k0 = ks * 16, kc = k0 + 2 * lc;
        float b00 = W1[(size_t)kc * H1D + n0];
        float b01 = W1[(size_t)(kc + 1) * H1D + n0];
        float b10 = W1[(size_t)(kc + 8) * H1D + n0];
        float b11 = W1[(size_t)(kc + 9) * H1D + n0];
        uint2 h;
        h.x = hpack2(b00, b01);
        h.y = hpack2(b10, b11);
        int idx = (gb * 32 + ks) * 32 + lane;
        g_WBh[idx] = h;
    }
}

// ================= xw1: 128x128 tiles, 256 threads, 2-term fp16 (R12 form) ==========
__global__ void __launch_bounds__(256) xw1_mma_kernel(__half* __restrict__ C) {
    int tid = threadIdx.x;
    int lane = tid & 31, warp = tid >> 5;
    int wr = warp >> 2, wc = warp & 3;
    int lr = lane >> 2, lc = lane & 3;
    int ga0 = blockIdx.y * 8 + wr * 4;
    int gb0 = blockIdx.x * 16 + wc * 4;

    float acc[4][4][4];
#pragma unroll
    for (int m = 0; m < 4; m++)
#pragma unroll
        for (int n = 0; n < 4; n++)
#pragma unroll
            for (int q = 0; q < 4; q++) acc[m][n][q] = 0.f;

    for (int ks = 0; ks < 32; ks++) {
        uint4 ah[4], al[4];
        uint2 bh[4];
#pragma unroll
        for (int mf = 0; mf < 4; mf++) {
            int ia = ((ga0 + mf) * 32 + ks) * 32 + lane;
            ah[mf] = g_XAh[ia];
            al[mf] = g_XAl[ia];
        }
#pragma unroll
        for (int nf = 0; nf < 4; nf++) {
            int ib = ((gb0 + nf) * 32 + ks) * 32 + lane;
            bh[nf] = g_WBh[ib];
        }
#pragma unroll
        for (int mf = 0; mf < 4; mf++)
#pragma unroll
            for (int nf = 0; nf < 4; nf++) mma_u4(acc[mf][nf], ah[mf], bh[nf]);
#pragma unroll
        for (int mf = 0; mf < 4; mf++)
#pragma unroll
            for (int nf = 0; nf < 4; nf++) mma_u4(acc[mf][nf], al[mf], bh[nf]);
    }
#pragma unroll
    for (int mf = 0; mf < 4; mf++) {
        int r = blockIdx.y * 128 + wr * 64 + mf * 16 + lr;
#pragma unroll
        for (int nf = 0; nf < 4; nf++) {
            int j = blockIdx.x * 128 + wc * 32 + nf * 8 + 2 * lc;
            *(__half2*)&C[(size_t)r * H1D + j] =
                __floats2half2_rn(acc[mf][nf][0], acc[mf][nf][1]);
            *(__half2*)&C[(size_t)(r + 8) * H1D + j] =
                __floats2half2_rn(acc[mf][nf][2], acc[mf][nf][3]);
        }
    }
}

// ================= CSR build =================
__global__ void hist_kernel(const int* __restrict__ rows) {
    int i = blockIdx.x * 256 + threadIdx.x;
    int4 r = ((const int4*)rows)[i];
    atomicAdd(&g_cnt[r.x], 1);
    atomicAdd(&g_cnt[r.y], 1);
    atomicAdd(&g_cnt[r.z], 1);
    atomicAdd(&g_cnt[r.w], 1);
}

__global__ void scan_kernel() {
    __shared__ int wtot[32];
    __shared__ int wexc[32];
    int t = threadIdx.x;
    int lane = t & 31, warp = t >> 5;
    int4 a = ((const int4*)g_cnt)[t * 2];
    int4 b = ((const int4*)g_cnt)[t * 2 + 1];
    int s8 = a.x + a.y + a.z + a.w + b.x + b.y + b.z + b.w;
    int inc = s8;
#pragma unroll
    for (int d = 1; d < 32; d <<= 1) {
        int v = __shfl_up_sync(0xffffffff, inc, d);
        if (lane >= d) inc += v;
    }
    if (lane == 31) wtot[warp] = inc;
    __syncthreads();
    if (warp == 0) {
        int v = wtot[lane];
        int wi = v;
#pragma unroll
        for (int d = 1; d < 32; d <<= 1) {
            int u = __shfl_up_sync(0xffffffff, wi, d);
            if (lane >= d) wi += u;
        }
        wexc[lane] = wi - v;
        if (lane == 31) g_rp[NN] = wi;
    }
    __syncthreads();
    int base = wexc[warp] + inc - s8;
    int o = base;
    g_rp[t * 8 + 0] = o; o += a.x;
    g_rp[t * 8 + 1] = o; o += a.y;
    g_rp[t * 8 + 2] = o; o += a.z;
    g_rp[t * 8 + 3] = o; o += a.w;
    g_rp[t * 8 + 4] = o; o += b.x;
    g_rp[t * 8 + 5] = o; o += b.y;
    g_rp[t * 8 + 6] = o; o += b.z;
    g_rp[t * 8 + 7] = o;
}

__global__ void scatter_kernel(const int* __restrict__ rows, const int* __restrict__ cols,
                               const float* __restrict__ vals) {
    int e = blockIdx.x * 256 + threadIdx.x;
    int r = rows[e];
    int old = atomicSub(&g_cnt[r], 1);
    int pos = g_rp[r] + old - 1;
    g_colval[pos] = make_int2(cols[e], __float_as_int(vals[e]));
}

// ================= SpMM (half in, half out + relu) =================
__global__ void spmm_h2h(const __half* __restrict__ X, __half* __restrict__ Y) {
    int r = blockIdx.x * 4 + (threadIdx.x >> 6);
    int t = threadIdx.x & 63;
    int s = g_rp[r], e = g_rp[r + 1];
    const uint2* Xu = (const uint2*)X;
    float4 acc = make_float4(0.f, 0.f, 0.f, 0.f);
    int i = s;
    for (; i + 4 <= e; i += 4) {
        int2 c0 = g_colval[i], c1 = g_colval[i + 1], c2 = g_colval[i + 2], c3 = g_colval[i + 3];
        uint2 r0 = Xu[(size_t)c0.x * 64 + t];
        uint2 r1 = Xu[(size_t)c1.x * 64 + t];
        uint2 r2 = Xu[(size_t)c2.x * 64 + t];
        uint2 r3 = Xu[(size_t)c3.x * 64 + t];
        float v0 = __int_as_float(c0.y), v1 = __int_as_float(c1.y);
        float v2 = __int_as_float(c2.y), v3 = __int_as_float(c3.y);
        float2 a0 = __half22float2(*(__half2*)&r0.x), b0 = __half22float2(*(__half2*)&r0.y);
        float2 a1 = __half22float2(*(__half2*)&r1.x), b1 = __half22float2(*(__half2*)&r1.y);
        float2 a2 = __half22float2(*(__half2*)&r2.x), b2 = __half22float2(*(__half2*)&r2.y);
        float2 a3 = __half22float2(*(__half2*)&r3.x), b3 = __half22float2(*(__half2*)&r3.y);
        acc.x += v0 * a0.x + v1 * a1.x + v2 * a2.x + v3 * a3.x;
        acc.y += v0 * a0.y + v1 * a1.y + v2 * a2.y + v3 * a3.y;
        acc.z += v0 * b0.x + v1 * b1.x + v2 * b2.x + v3 * b3.x;
        acc.w += v0 * b0.y + v1 * b1.y + v2 * b2.y + v3 * b3.y;
    }
    for (; i < e; i++) {
        int2 c = g_colval[i];
        uint2 rv = Xu[(size_t)c.x * 64 + t];
        float v = __int_as_float(c.y);
        float2 a = __half22float2(*(__half2*)&rv.x), b = __half22float2(*(__half2*)&rv.y);
        acc.x += v * a.x; acc.y += v * a.y; acc.z += v * b.x; acc.w += v * b.y;
    }
    uint2 out;
    __half2 o0 = __floats2half2_rn(fmaxf(acc.x, 0.f), fmaxf(acc.y, 0.f));
    __half2 o1 = __floats2half2_rn(fmaxf(acc.z, 0.f), fmaxf(acc.w, 0.f));
    out.x = *(unsigned*)&o0;
    out.y = *(unsigned*)&o1;
    ((uint2*)Y)[(size_t)r * 64 + t] = out;
}

// ================= SpMM (half in, float out, no relu) =================
__global__ void spmm_h2f(const __half* __restrict__ X, float* __restrict__ Y) {
    int r = blockIdx.x * 4 + (threadIdx.x >> 6);
    int t = threadIdx.x & 63;
    int s = g_rp[r], e = g_rp[r + 1];
    const uint2* Xu = (const uint2*)X;
    float4 acc = make_float4(0.f, 0.f, 0.f, 0.f);
    int i = s;
    for (; i + 4 <= e; i += 4) {
        int2 c0 = g_colval[i], c1 = g_colval[i + 1], c2 = g_colval[i + 2], c3 = g_colval[i + 3];
        uint2 r0 = Xu[(size_t)c0.x * 64 + t];
        uint2 r1 = Xu[(size_t)c1.x * 64 + t];
        uint2 r2 = Xu[(size_t)c2.x * 64 + t];
        uint2 r3 = Xu[(size_t)c3.x * 64 + t];
        float v0 = __int_as_float(c0.y), v1 = __int_as_float(c1.y);
        float v2 = __int_as_float(c2.y), v3 = __int_as_float(c3.y);
        float2 a0 = __half22float2(*(__half2*)&r0.x), b0 = __half22float2(*(__half2*)&r0.y);
        float2 a1 = __half22float2(*(__half2*)&r1.x), b1 = __half22float2(*(__half2*)&r1.y);
        float2 a2 = __half22float2(*(__half2*)&r2.x), b2 = __half22float2(*(__half2*)&r2.y);
        float2 a3 = __half22float2(*(__half2*)&r3.x), b3 = __half22float2(*(__half2*)&r3.y);
        acc.x += v0 * a0.x + v1 * a1.x + v2 * a2.x + v3 * a3.x;
        acc.y += v0 * a0.y + v1 * a1.y + v2 * a2.y + v3 * a3.y;
        acc.z += v0 * b0.x + v1 * b1.x + v2 * b2.x + v3 * b3.x;
        acc.w += v0 * b0.y + v1 * b1.y + v2 * b2.y + v3 * b3.y;
    }
    for (; i < e; i++) {
        int2 c = g_colval[i];
        uint2 rv = Xu[(size_t)c.x * 64 + t];
        float v = __int_as_float(c.y);
        float2 a = __half22float2(*(__half2*)&rv.x), b = __half22float2(*(__half2*)&rv.y);
        acc.x += v * a.x; acc.y += v * a.y; acc.z += v * b.x; acc.w += v * b.y;
    }
    ((float4*)Y)[(size_t)r * 64 + t] = acc;
}

// ================= Wcat = [W2@dense_W | W3@dense_W] =================
__global__ void wcat_kernel(const float* __restrict__ W2, const float* __restrict__ W3,
                            const float* __restrict__ dW) {
    int k = blockIdx.x;
    int c = threadIdx.x;
    const float* Ws = (c < 64) ? W2 : W3;
    int cc = c & 63;
    float a = 0.f;
#pragma unroll 4
    for (int j = 0; j < H2D; j++) a += Ws[k * H2D + j] * dW[j * H3D + cc];
    g_Wcat[k * H2D + c] = a;
}

// ========== fused: mu/lv = ah1@Wcat + bias, + mu frag packs + o6, one kernel ==========
__global__ void __launch_bounds__(256) ml_fused_kernel(
    const float* __restrict__ A, const float* __restrict__ db,
    const float* __restrict__ d1W, const float* __restrict__ d1b,
    float* __restrict__ mu, float* __restrict__ lv, float* __restrict__ o6) {
    const int BK = 16;
    __shared__ float As[BK][132];
    __shared__ float Bs[BK][132];
    __shared__ unsigned muS[128][34];
    __shared__ float w6[64 * O6];
    __shared__ float b6[O6];
    int tid = threadIdx.x;
    for (int i = tid; i < 64 * O6; i += 256) w6[i] = d1W[i];
    if (tid < O6) b6[tid] = d1b[tid];
    int tx = tid & 15, ty = tid >> 4;
    int row0 = blockIdx.x * 128;
    float acc[8][8];
#pragma unroll
    for (int r = 0; r < 8; r++)
#pragma unroll
        for (int c = 0; c < 8; c++) acc[r][c] = 0.f;
    for (int k0 = 0; k0 < H1D; k0 += BK) {
#pragma unroll
        for (int i = 0; i < 2; i++) {
            int idx = tid + i * 256;
            int ar = idx >> 2, kq = (idx & 3) * 4;
            float4 v = *(const float4*)&A[(size_t)(row0 + ar) * H1D + k0 + kq];
            As[kq + 0][ar] = v.x; As[kq + 1][ar] = v.y;
            As[kq + 2][ar] = v.z; As[kq + 3][ar] = v.w;
        }
        {
            int br = tid >> 5, bc = (tid & 31) * 4;
            *(float4*)&Bs[br][bc] = *(const float4*)&g_Wcat[(k0 + br) * H2D + bc];
            *(float4*)&Bs[br + 8][bc] = *(const float4*)&g_Wcat[(k0 + br + 8) * H2D + bc];
        }
        __syncthreads();
#pragma unroll
        for (int kk = 0; kk < BK; kk++) {
            float a[8], b[8];
            *(float4*)&a[0] = *(float4*)&As[kk][ty * 8];
            *(float4*)&a[4] = *(float4*)&As[kk][ty * 8 + 4];
            *(float4*)&b[0] = *(float4*)&Bs[kk][tx * 8];
            *(float4*)&b[4] = *(float4*)&Bs[kk][tx * 8 + 4];
#pragma unroll
            for (int r = 0; r < 8; r++)
#pragma unroll
                for (int c = 0; c < 8; c++) acc[r][c] += a[r] * b[c];
        }
        __syncthreads();
    }
    int colg = tx * 8;
    float bias[8];
#pragma unroll
    for (int c = 0; c < 8; c++) bias[c] = __ldg(&db[(colg + c) & 63]);
    int cc = colg & 63;
    float* dst = (colg < 64) ? mu : lv;
#pragma unroll
    for (int r = 0; r < 8; r++) {
        int rl = ty * 8 + r;
        int rg = row0 + rl;
        float v[8];
#pragma unroll
        for (int c = 0; c < 8; c++) v[c] = acc[r][c] + bias[c];
        *(float4*)&dst[(size_t)rg * 64 + cc] = make_float4(v[0], v[1], v[2], v[3]);
        *(float4*)&dst[(size_t)rg * 64 + cc + 4] = make_float4(v[4], v[5], v[6], v[7]);
        if (colg < 64) {
#pragma unroll
            for (int q = 0; q < 4; q++)
                muS[rl][(colg >> 1) + q] = hpack2(v[2 * q], v[2 * q + 1]);
        }
    }
    __syncthreads();
    // A-frag pack
    for (int i = tid; i < 1024; i += 256) {
        int gl = i >> 7, ks = (i >> 5) & 3, lane = i & 31;
        int lr = lane >> 2, lc = lane & 3;
        int rl = gl * 16 + lr;
        int ci = ks * 8 + lc;
        uint4 h;
        h.x = muS[rl][ci];
        h.y = muS[rl + 8][ci];
        h.z = muS[rl][ci + 4];
        h.w = muS[rl + 8][ci + 4];
        g_MAh[((row0 / 16 + gl) * 4 + ks) * 32 + lane] = h;
    }
    // B-frag pack
    for (int i = tid; i < 2048; i += 256) {
        int gl = i >> 7, ks = (i >> 5) & 3, lane = i & 31;
        int lr = lane >> 2, lc = lane & 3;
        int nl = gl * 8 + lr;
        int ci = ks * 8 + lc;
        uint2 h;
        h.x = muS[nl][ci];
        h.y = muS[nl][ci + 4];
        g_MBh[((row0 / 8 + gl) * 4 + ks) * 32 + lane] = h;
    }
    // o6
    for (int i = tid; i < 128 * O6; i += 256) {
        int rl = i / O6, c = i - rl * O6;
        float a = b6[c];
#pragma unroll 8
        for (int k = 0; k < 32; k++) {
            unsigned p = muS[rl][k];
            float2 f = __half22float2(*(__half2*)&p);
            a += f.x * w6[(2 * k) * O6 + c] + f.y * w6[(2 * k + 1) * O6 + c];
        }
        o6[(size_t)(row0 + rl) * O6 + c] = a;
    }
}

// ================= zzt: 128 threads, warp tile 64x64, mirror, 1-term fp16 ==========
__global__ void __launch_bounds__(128) zzt_kernel(float* __restrict__ C) {
    int bx = blockIdx.x, by = blockIdx.y;
    if (by > bx) return;
    __shared__ float T[32][132];
    int tid = threadIdx.x;
    int lane = tid & 31, warp = tid >> 5;
    int wr = warp >> 1, wc = warp & 1;
    int lr = lane >> 2, lc = lane & 3;
    int i0 = by * 128, j0 = bx * 128;
    int ga0 = by * 8 + wr * 4;
    int gb0 = bx * 16 + wc * 8;

    float acc[4][8][4];
#pragma unroll
    for (int m = 0; m < 4; m++)
#pragma unroll
        for (int n = 0; n < 8; n++)
#pragma unroll
            for (int q = 0; q < 4; q++) acc[m][n][q] = 0.f;

#pragma unroll
    for (int ks = 0; ks < 4; ks++) {
        uint4 ah[4];
        uint2 bh[8];
#pragma unroll
        for (int mf = 0; mf < 4; mf++) {
            int ia = ((ga0 + mf) * 4 + ks) * 32 + lane;
            ah[mf] = g_MAh[ia];
        }
#pragma unroll
        for (int nf = 0; nf < 8; nf++) {
            int ib = ((gb0 + nf) * 4 + ks) * 32 + lane;
            bh[nf] = g_MBh[ib];
        }
#pragma unroll
        for (int mf = 0; mf < 4; mf++)
#pragma unroll
            for (int nf = 0; nf < 8; nf++) mma_u4(acc[mf][nf], ah[mf], bh[nf]);
    }
    // direct tile
#pragma unroll
    for (int mf = 0; mf < 4; mf++) {
        int r = i0 + wr * 64 + mf * 16 + lr;
#pragma unroll
        for (int nf = 0; nf < 8; nf++) {
            int j = j0 + wc * 64 + nf * 8 + 2 * lc;
            *(float2*)&C[(size_t)r * NN + j] = make_float2(acc[mf][nf][0], acc[mf][nf][1]);
            *(float2*)&C[(size_t)(r + 8) * NN + j] = make_float2(acc[mf][nf][2], acc[mf][nf][3]);
        }
    }
    if (bx == by) return;
    // mirror: 4 strips of 32 cols via smem transpose
#pragma unroll
    for (int s = 0; s < 4; s++) {
        __syncthreads();
        if (wc == (s >> 1)) {
            int nf0 = (s & 1) * 4;
#pragma unroll
            for (int mf = 0; mf < 4; mf++) {
                int rl = wr * 64 + mf * 16 + lr;
#pragma unroll
                for (int nf = 0; nf < 4; nf++) {
                    int cl = nf * 8 + 2 * lc;
                    T[cl][rl] = acc[mf][nf0 + nf][0];
                    T[cl + 1][rl] = acc[mf][nf0 + nf][1];
                    T[cl][rl + 8] = acc[mf][nf0 + nf][2];
                    T[cl + 1][rl + 8] = acc[mf][nf0 + nf][3];
                }
            }
        }
        __syncthreads();
        int jj = tid >> 2, seg = (tid & 3) * 32;
        size_t base = (size_t)(j0 + s * 32 + jj) * NN + i0 + seg;
#pragma unroll
        for (int q = 0; q < 8; q++)
            *(float4*)&C[base + q * 4] = *(float4*)&T[jj][seg + q * 4];
    }
}

// ================= launch =================
extern "C" void kernel_launch(void* const* d_in, const int* in_sizes, int n_in,
                              void* d_out, int out_size) {
    const float* x        = (const float*)d_in[0];
    const int*   adj_rows = (const int*)d_in[1];
    const int*   adj_cols = (const int*)d_in[2];
    const float* adj_vals = (const float*)d_in[3];
    const float* W1       = (const float*)d_in[4];
    const float* W2       = (const float*)d_in[5];
    const float* W3       = (const float*)d_in[6];
    const float* dense_W  = (const float*)d_in[7];
    const float* dense_b  = (const float*)d_in[8];
    const float* dense1_W = (const float*)d_in[9];
    const float* dense1_b = (const float*)d_in[10];

    float* out = (float*)d_out;
    float* adj = out;
    float* o6  = adj + (size_t)NN * NN;
    float* mu  = o6 + (size_t)NN * O6;
    float* lv  = mu + (size_t)NN * H3D;

    void *p_xw1h, *p_h1h, *p_ah1;
    cudaGetSymbolAddress(&p_xw1h, g_xw1h);
    cudaGetSymbolAddress(&p_h1h, g_h1h);
    cudaGetSymbolAddress(&p_ah1, g_ah1);

    // prep packs + small weights
    wcat_kernel<<<H1D, H2D>>>(W2, W3, dense_W);
    pack_inputs_kernel<<<544, 1024>>>(x, W1);

    // xw1 = x @ W1 (fp16 2-term, R12 non-pipelined form)
    xw1_mma_kernel<<<dim3(2, 64), 256>>>((__half*)p_xw1h);

    // CSR
    hist_kernel<<<NE / 1024, 256>>>(adj_rows);
    scan_kernel<<<1, 1024>>>();
    scatter_kernel<<<NE / 256, 256>>>(adj_rows, adj_cols, adj_vals);

    // SpMMs (half storage)
    spmm_h2h<<<NN / 4, 256>>>((const __half*)p_xw1h, (__half*)p_h1h);
    spmm_h2f<<<NN / 4, 256>>>((const __half*)p_h1h, (float*)p_ah1);

    // mu/lv + frag packs + o6, fused
    ml_fused_kernel<<<NN / 128, 256>>>((const float*)p_ah1, dense_b, dense1_W, dense1_b,
                                       mu, lv, o6);

    // adj_rec = mu @ mu^T (half grid + mirror, fp16 1-term)
    zzt_kernel<<<dim3(64, 64), 128>>>(adj);
}

// round 17
// speedup vs baseline: 1.4986x; 1.0477x over previous
#include <cuda_runtime.h>
#include <cuda_fp16.h>
#include <cstdint>

#define NN 8192
#define NE 262144
#define FIN 512
#define H1D 256
#define H2D 128
#define H3D 64
#define O6 6

// ---------------- device scratch ----------------
__device__ __half g_xw1h[NN * H1D];
__device__ __half g_h1h[NN * H1D];
__device__ float  g_ah1[NN * H1D];
__device__ float  g_Wcat[H1D * H2D];
__device__ int    g_cnt[NN];          // zero-init; invariant: returns to 0 after scatter
__device__ int    g_rp[NN + 1];
__device__ int2   g_colval[NE];
__device__ uint4 g_XAh[512 * 32 * 32];
__device__ uint4 g_XAl[512 * 32 * 32];
__device__ uint2 g_WBh[32 * 32 * 32];
__device__ uint4 g_MAh[512 * 4 * 32];
__device__ uint2 g_MBh[1024 * 4 * 32];

// ---------------- fp16 helpers ----------------
__device__ __forceinline__ void hsplit2(float x0, float x1, unsigned& hp, unsigned& lp) {
    __half h0 = __float2half_rn(x0), h1 = __float2half_rn(x1);
    float r0 = x0 - __half2float(h0), r1 = x1 - __half2float(h1);
    __half l0 = __float2half_rn(r0), l1 = __float2half_rn(r1);
    hp = (unsigned)__half_as_ushort(h0) | ((unsigned)__half_as_ushort(h1) << 16);
    lp = (unsigned)__half_as_ushort(l0) | ((unsigned)__half_as_ushort(l1) << 16);
}
__device__ __forceinline__ unsigned hpack2(float x0, float x1) {
    __half h0 = __float2half_rn(x0), h1 = __float2half_rn(x1);
    return (unsigned)__half_as_ushort(h0) | ((unsigned)__half_as_ushort(h1) << 16);
}

__device__ __forceinline__ void mma_u4(float* c, const uint4& a, const uint2& b) {
    asm volatile(
        "mma.sync.aligned.m16n8k16.row.col.f32.f16.f16.f32 "
        "{%0,%1,%2,%3}, {%4,%5,%6,%7}, {%8,%9}, {%0,%1,%2,%3};"
        : "+f"(c[0]), "+f"(c[1]), "+f"(c[2]), "+f"(c[3])
        : "r"(a.x), "r"(a.y), "r"(a.z), "r"(a.w), "r"(b.x), "r"(b.y));
}

// ================= pack x (blocks 0..511) + W1 (blocks 512..543) =================
__global__ void pack_inputs_kernel(const float* __restrict__ x, const float* __restrict__ W1) {
    int lane = threadIdx.x & 31, ks = threadIdx.x >> 5;
    int lr = lane >> 2, lc = lane & 3;
    if (blockIdx.x < 512) {
        int g = blockIdx.x;
        int row0 = g * 16 + lr, k0 = ks * 16, c0 = k0 + 2 * lc;
        float2 v0 = *(const float2*)&x[(size_t)row0 * FIN + c0];
        float2 v1 = *(const float2*)&x[(size_t)(row0 + 8) * FIN + c0];
        float2 v2 = *(const float2*)&x[(size_t)row0 * FIN + c0 + 8];
        float2 v3 = *(const float2*)&x[(size_t)(row0 + 8) * FIN + c0 + 8];
        uint4 h, l;
        hsplit2(v0.x, v0.y, h.x, l.x);
        hsplit2(v1.x, v1.y, h.y, l.y);
        hsplit2(v2.x, v2.y, h.z, l.z);
        hsplit2(v3.x, v3.y, h.w, l.w);
        int idx = (g * 32 + ks) * 32 + lane;
        g_XAh[idx] = h;
        g_XAl[idx] = l;
    } else {
        int gb = blockIdx.x - 512;
        int n0 = gb * 8 + lr, k0 = ks * 16, kc = k0 + 2 * lc;
        float b00 = W1[(size_t)kc * H1D + n0];
        float b01 = W1[(size_t)(kc + 1) * H1D + n0];
        float b10 = W1[(size_t)(kc + 8) * H1D + n0];
        float b11 = W1[(size_t)(kc + 9) * H1D + n0];
        uint2 h;
        h.x = hpack2(b00, b01);
        h.y = hpack2(b10, b11);
        int idx = (gb * 32 + ks) * 32 + lane;
        g_WBh[idx] = h;
    }
}

// ================= xw1: 128x128 tiles, 256 threads, 2-term fp16 =================
__global__ void __launch_bounds__(256) xw1_mma_kernel(__half* __restrict__ C) {
    int tid = threadIdx.x;
    int lane = tid & 31, warp = tid >> 5;
    int wr = warp >> 2, wc = warp & 3;
    int lr = lane >> 2, lc = lane & 3;
    int ga0 = blockIdx.y * 8 + wr * 4;
    int gb0 = blockIdx.x * 16 + wc * 4;

    float acc[4][4][4];
#pragma unroll
    for (int m = 0; m < 4; m++)
#pragma unroll
        for (int n = 0; n < 4; n++)
#pragma unroll
            for (int q = 0; q < 4; q++) acc[m][n][q] = 0.f;

    for (int ks = 0; ks < 32; ks++) {
        uint4 ah[4], al[4];
        uint2 bh[4];
#pragma unroll
        for (int mf = 0; mf < 4; mf++) {
            int ia = ((ga0 + mf) * 32 + ks) * 32 + lane;
            ah[mf] = g_XAh[ia];
            al[mf] = g_XAl[ia];
        }
#pragma unroll
        for (int nf = 0; nf < 4; nf++) {
            int ib = ((gb0 + nf) * 32 + ks) * 32 + lane;
            bh[nf] = g_WBh[ib];
        }
#pragma unroll
        for (int mf = 0; mf < 4; mf++)
#pragma unroll
            for (int nf = 0; nf < 4; nf++) mma_u4(acc[mf][nf], ah[mf], bh[nf]);
#pragma unroll
        for (int mf = 0; mf < 4; mf++)
#pragma unroll
            for (int nf = 0; nf < 4; nf++) mma_u4(acc[mf][nf], al[mf], bh[nf]);
    }
#pragma unroll
    for (int mf = 0; mf < 4; mf++) {
        int r = blockIdx.y * 128 + wr * 64 + mf * 16 + lr;
#pragma unroll
        for (int nf = 0; nf < 4; nf++) {
            int j = blockIdx.x * 128 + wc * 32 + nf * 8 + 2 * lc;
            *(__half2*)&C[(size_t)r * H1D + j] =
                __floats2half2_rn(acc[mf][nf][0], acc[mf][nf][1]);
            *(__half2*)&C[(size_t)(r + 8) * H1D + j] =
                __floats2half2_rn(acc[mf][nf][2], acc[mf][nf][3]);
        }
    }
}

// ================= CSR build =================
__global__ void hist_kernel(const int* __restrict__ rows) {
    int e = blockIdx.x * 256 + threadIdx.x;
    atomicAdd(&g_cnt[rows[e]], 1);
}

__global__ void scan_kernel() {
    __shared__ int wtot[32];
    __shared__ int wexc[32];
    int t = threadIdx.x;
    int lane = t & 31, warp = t >> 5;
    int4 a = ((const int4*)g_cnt)[t * 2];
    int4 b = ((const int4*)g_cnt)[t * 2 + 1];
    int s8 = a.x + a.y + a.z + a.w + b.x + b.y + b.z + b.w;
    int inc = s8;
#pragma unroll
    for (int d = 1; d < 32; d <<= 1) {
        int v = __shfl_up_sync(0xffffffff, inc, d);
        if (lane >= d) inc += v;
    }
    if (lane == 31) wtot[warp] = inc;
    __syncthreads();
    if (warp == 0) {
        int v = wtot[lane];
        int wi = v;
#pragma unroll
        for (int d = 1; d < 32; d <<= 1) {
            int u = __shfl_up_sync(0xffffffff, wi, d);
            if (lane >= d) wi += u;
        }
        wexc[lane] = wi - v;
        if (lane == 31) g_rp[NN] = wi;
    }
    __syncthreads();
    int base = wexc[warp] + inc - s8;
    int o = base;
    g_rp[t * 8 + 0] = o; o += a.x;
    g_rp[t * 8 + 1] = o; o += a.y;
    g_rp[t * 8 + 2] = o; o += a.z;
    g_rp[t * 8 + 3] = o; o += a.w;
    g_rp[t * 8 + 4] = o; o += b.x;
    g_rp[t * 8 + 5] = o; o += b.y;
    g_rp[t * 8 + 6] = o; o += b.z;
    g_rp[t * 8 + 7] = o;
}

__global__ void scatter_kernel(const int* __restrict__ rows, const int* __restrict__ cols,
                               const float* __restrict__ vals) {
    int e = blockIdx.x * 256 + threadIdx.x;
    int r = rows[e];
    int old = atomicSub(&g_cnt[r], 1);
    int pos = g_rp[r] + old - 1;
    g_colval[pos] = make_int2(cols[e], __float_as_int(vals[e]));
}

// ================= SpMM (half in, half out + relu) =================
__global__ void spmm_h2h(const __half* __restrict__ X, __half* __restrict__ Y) {
    int r = blockIdx.x * 4 + (threadIdx.x >> 6);
    int t = threadIdx.x & 63;
    int s = g_rp[r], e = g_rp[r + 1];
    const uint2* Xu = (const uint2*)X;
    float4 acc = make_float4(0.f, 0.f, 0.f, 0.f);
    int i = s;
    for (; i + 4 <= e; i += 4) {
        int2 c0 = g_colval[i], c1 = g_colval[i + 1], c2 = g_colval[i + 2], c3 = g_colval[i + 3];
        uint2 r0 = Xu[(size_t)c0.x * 64 + t];
        uint2 r1 = Xu[(size_t)c1.x * 64 + t];
        uint2 r2 = Xu[(size_t)c2.x * 64 + t];
        uint2 r3 = Xu[(size_t)c3.x * 64 + t];
        float v0 = __int_as_float(c0.y), v1 = __int_as_float(c1.y);
        float v2 = __int_as_float(c2.y), v3 = __int_as_float(c3.y);
        float2 a0 = __half22float2(*(__half2*)&r0.x), b0 = __half22float2(*(__half2*)&r0.y);
        float2 a1 = __half22float2(*(__half2*)&r1.x), b1 = __half22float2(*(__half2*)&r1.y);
        float2 a2 = __half22float2(*(__half2*)&r2.x), b2 = __half22float2(*(__half2*)&r2.y);
        float2 a3 = __half22float2(*(__half2*)&r3.x), b3 = __half22float2(*(__half2*)&r3.y);
        acc.x += v0 * a0.x + v1 * a1.x + v2 * a2.x + v3 * a3.x;
        acc.y += v0 * a0.y + v1 * a1.y + v2 * a2.y + v3 * a3.y;
        acc.z += v0 * b0.x + v1 * b1.x + v2 * b2.x + v3 * b3.x;
        acc.w += v0 * b0.y + v1 * b1.y + v2 * b2.y + v3 * b3.y;
    }
    for (; i < e; i++) {
        int2 c = g_colval[i];
        uint2 rv = Xu[(size_t)c.x * 64 + t];
        float v = __int_as_float(c.y);
        float2 a = __half22float2(*(__half2*)&rv.x), b = __half22float2(*(__half2*)&rv.y);
        acc.x += v * a.x; acc.y += v * a.y; acc.z += v * b.x; acc.w += v * b.y;
    }
    uint2 out;
    __half2 o0 = __floats2half2_rn(fmaxf(acc.x, 0.f), fmaxf(acc.y, 0.f));
    __half2 o1 = __floats2half2_rn(fmaxf(acc.z, 0.f), fmaxf(acc.w, 0.f));
    out.x = *(unsigned*)&o0;
    out.y = *(unsigned*)&o1;
    ((uint2*)Y)[(size_t)r * 64 + t] = out;
}

// ================= SpMM (half in, float out, no relu) =================
__global__ void spmm_h2f(const __half* __restrict__ X, float* __restrict__ Y) {
    int r = blockIdx.x * 4 + (threadIdx.x >> 6);
    int t = threadIdx.x & 63;
    int s = g_rp[r], e = g_rp[r + 1];
    const uint2* Xu = (const uint2*)X;
    float4 acc = make_float4(0.f, 0.f, 0.f, 0.f);
    int i = s;
    for (; i + 4 <= e; i += 4) {
        int2 c0 = g_colval[i], c1 = g_colval[i + 1], c2 = g_colval[i + 2], c3 = g_colval[i + 3];
        uint2 r0 = Xu[(size_t)c0.x * 64 + t];
        uint2 r1 = Xu[(size_t)c1.x * 64 + t];
        uint2 r2 = Xu[(size_t)c2.x * 64 + t];
        uint2 r3 = Xu[(size_t)c3.x * 64 + t];
        float v0 = __int_as_float(c0.y), v1 = __int_as_float(c1.y);
        float v2 = __int_as_float(c2.y), v3 = __int_as_float(c3.y);
        float2 a0 = __half22float2(*(__half2*)&r0.x), b0 = __half22float2(*(__half2*)&r0.y);
        float2 a1 = __half22float2(*(__half2*)&r1.x), b1 = __half22float2(*(__half2*)&r1.y);
        float2 a2 = __half22float2(*(__half2*)&r2.x), b2 = __half22float2(*(__half2*)&r2.y);
        float2 a3 = __half22float2(*(__half2*)&r3.x), b3 = __half22float2(*(__half2*)&r3.y);
        acc.x += v0 * a0.x + v1 * a1.x + v2 * a2.x + v3 * a3.x;
        acc.y += v0 * a0.y + v1 * a1.y + v2 * a2.y + v3 * a3.y;
        acc.z += v0 * b0.x + v1 * b1.x + v2 * b2.x + v3 * b3.x;
        acc.w += v0 * b0.y + v1 * b1.y + v2 * b2.y + v3 * b3.y;
    }
    for (; i < e; i++) {
        int2 c = g_colval[i];
        uint2 rv = Xu[(size_t)c.x * 64 + t];
        float v = __int_as_float(c.y);
        float2 a = __half22float2(*(__half2*)&rv.x), b = __half22float2(*(__half2*)&rv.y);
        acc.x += v * a.x; acc.y += v * a.y; acc.z += v * b.x; acc.w += v * b.y;
    }
    ((float4*)Y)[(size_t)r * 64 + t] = acc;
}

// ================= Wcat = [W2@dense_W | W3@dense_W] =================
__global__ void wcat_kernel(const float* __restrict__ W2, const float* __restrict__ W3,
                            const float* __restrict__ dW) {
    int k = blockIdx.x;
    int c = threadIdx.x;
    const float* Ws = (c < 64) ? W2 : W3;
    int cc = c & 63;
    float a = 0.f;
#pragma unroll 4
    for (int j = 0; j < H2D; j++) a += Ws[k * H2D + j] * dW[j * H3D + cc];
    g_Wcat[k * H2D + c] = a;
}

// ========== fused: mu/lv = ah1@Wcat + bias, + mu frag packs + o6 ==========
__global__ void __launch_bounds__(256) ml_fused_kernel(
    const float* __restrict__ A, const float* __restrict__ db,
    const float* __restrict__ d1W, const float* __restrict__ d1b,
    float* __restrict__ mu, float* __restrict__ lv, float* __restrict__ o6) {
    const int BK = 16;
    __shared__ float As[BK][132];
    __shared__ float Bs[BK][132];
    __shared__ unsigned muS[128][34];
    __shared__ float w6[64 * O6];
    __shared__ float b6[O6];
    int tid = threadIdx.x;
    for (int i = tid; i < 64 * O6; i += 256) w6[i] = d1W[i];
    if (tid < O6) b6[tid] = d1b[tid];
    int tx = tid & 15, ty = tid >> 4;
    int row0 = blockIdx.x * 128;
    float acc[8][8];
#pragma unroll
    for (int r = 0; r < 8; r++)
#pragma unroll
        for (int c = 0; c < 8; c++) acc[r][c] = 0.f;
    for (int k0 = 0; k0 < H1D; k0 += BK) {
#pragma unroll
        for (int i = 0; i < 2; i++) {
            int idx = tid + i * 256;
            int ar = idx >> 2, kq = (idx & 3) * 4;
            float4 v = *(const float4*)&A[(size_t)(row0 + ar) * H1D + k0 + kq];
            As[kq + 0][ar] = v.x; As[kq + 1][ar] = v.y;
            As[kq + 2][ar] = v.z; As[kq + 3][ar] = v.w;
        }
        {
            int br = tid >> 5, bc = (tid & 31) * 4;
            *(float4*)&Bs[br][bc] = *(const float4*)&g_Wcat[(k0 + br) * H2D + bc];
            *(float4*)&Bs[br + 8][bc] = *(const float4*)&g_Wcat[(k0 + br + 8) * H2D + bc];
        }
        __syncthreads();
#pragma unroll
        for (int kk = 0; kk < BK; kk++) {
            float a[8], b[8];
            *(float4*)&a[0] = *(float4*)&As[kk][ty * 8];
            *(float4*)&a[4] = *(float4*)&As[kk][ty * 8 + 4];
            *(float4*)&b[0] = *(float4*)&Bs[kk][tx * 8];
            *(float4*)&b[4] = *(float4*)&Bs[kk][tx * 8 + 4];
#pragma unroll
            for (int r = 0; r < 8; r++)
#pragma unroll
                for (int c = 0; c < 8; c++) acc[r][c] += a[r] * b[c];
        }
        __syncthreads();
    }
    int colg = tx * 8;
    float bias[8];
#pragma unroll
    for (int c = 0; c < 8; c++) bias[c] = __ldg(&db[(colg + c) & 63]);
    int cc = colg & 63;
    float* dst = (colg < 64) ? mu : lv;
#pragma unroll
    for (int r = 0; r < 8; r++) {
        int rl = ty * 8 + r;
        int rg = row0 + rl;
        float v[8];
#pragma unroll
        for (int c = 0; c < 8; c++) v[c] = acc[r][c] + bias[c];
        *(float4*)&dst[(size_t)rg * 64 + cc] = make_float4(v[0], v[1], v[2], v[3]);
        *(float4*)&dst[(size_t)rg * 64 + cc + 4] = make_float4(v[4], v[5], v[6], v[7]);
        if (colg < 64) {
#pragma unroll
            for (int q = 0; q < 4; q++)
                muS[rl][(colg >> 1) + q] = hpack2(v[2 * q], v[2 * q + 1]);
        }
    }
    __syncthreads();
    // A-frag pack
    for (int i = tid; i < 1024; i += 256) {
        int gl = i >> 7, ks = (i >> 5) & 3, lane = i & 31;
        int lr = lane >> 2, lc = lane & 3;
        int rl = gl * 16 + lr;
        int ci = ks * 8 + lc;
        uint4 h;
        h.x = muS[rl][ci];
        h.y = muS[rl + 8][ci];
        h.z = muS[rl][ci + 4];
        h.w = muS[rl + 8][ci + 4];
        g_MAh[((row0 / 16 + gl) * 4 + ks) * 32 + lane] = h;
    }
    // B-frag pack
    for (int i = tid; i < 2048; i += 256) {
        int gl = i >> 7, ks = (i >> 5) & 3, lane = i & 31;
        int lr = lane >> 2, lc = lane & 3;
        int nl = gl * 8 + lr;
        int ci = ks * 8 + lc;
        uint2 h;
        h.x = muS[nl][ci];
        h.y = muS[nl][ci + 4];
        g_MBh[((row0 / 8 + gl) * 4 + ks) * 32 + lane] = h;
    }
    // o6
    for (int i = tid; i < 128 * O6; i += 256) {
        int rl = i / O6, c = i - rl * O6;
        float a = b6[c];
#pragma unroll 8
        for (int k = 0; k < 32; k++) {
            unsigned p = muS[rl][k];
            float2 f = __half22float2(*(__half2*)&p);
            a += f.x * w6[(2 * k) * O6 + c] + f.y * w6[(2 * k + 1) * O6 + c];
        }
        o6[(size_t)(row0 + rl) * O6 + c] = a;
    }
}

// ================= zzt: 128 threads, warp tile 64x64, mirror, 1-term fp16 ==========
__global__ void __launch_bounds__(128) zzt_kernel(float* __restrict__ C) {
    int bx = blockIdx.x, by = blockIdx.y;
    if (by > bx) return;
    __shared__ float T[32][132];
    int tid = threadIdx.x;
    int lane = tid & 31, warp = tid >> 5;
    int wr = warp >> 1, wc = warp & 1;
    int lr = lane >> 2, lc = lane & 3;
    int i0 = by * 128, j0 = bx * 128;
    int ga0 = by * 8 + wr * 4;
    int gb0 = bx * 16 + wc * 8;

    float acc[4][8][4];
#pragma unroll
    for (int m = 0; m < 4; m++)
#pragma unroll
        for (int n = 0; n < 8; n++)
#pragma unroll
            for (int q = 0; q < 4; q++) acc[m][n][q] = 0.f;

#pragma unroll
    for (int ks = 0; ks < 4; ks++) {
        uint4 ah[4];
        uint2 bh[8];
#pragma unroll
        for (int mf = 0; mf < 4; mf++) {
            int ia = ((ga0 + mf) * 4 + ks) * 32 + lane;
            ah[mf] = g_MAh[ia];
        }
#pragma unroll
        for (int nf = 0; nf < 8; nf++) {
            int ib = ((gb0 + nf) * 4 + ks) * 32 + lane;
            bh[nf] = g_MBh[ib];
        }
#pragma unroll
        for (int mf = 0; mf < 4; mf++)
#pragma unroll
            for (int nf = 0; nf < 8; nf++) mma_u4(acc[mf][nf], ah[mf], bh[nf]);
    }
#pragma unroll
    for (int mf = 0; mf < 4; mf++) {
        int r = i0 + wr * 64 + mf * 16 + lr;
#pragma unroll
        for (int nf = 0; nf < 8; nf++) {
            int j = j0 + wc * 64 + nf * 8 + 2 * lc;
            *(float2*)&C[(size_t)r * NN + j] = make_float2(acc[mf][nf][0], acc[mf][nf][1]);
            *(float2*)&C[(size_t)(r + 8) * NN + j] = make_float2(acc[mf][nf][2], acc[mf][nf][3]);
        }
    }
    if (bx == by) return;
#pragma unroll
    for (int s = 0; s < 4; s++) {
        __syncthreads();
        if (wc == (s >> 1)) {
            int nf0 = (s & 1) * 4;
#pragma unroll
            for (int mf = 0; mf < 4; mf++) {
                int rl = wr * 64 + mf * 16 + lr;
#pragma unroll
                for (int nf = 0; nf < 4; nf++) {
                    int cl = nf * 8 + 2 * lc;
                    T[cl][rl] = acc[mf][nf0 + nf][0];
                    T[cl + 1][rl] = acc[mf][nf0 + nf][1];
                    T[cl][rl + 8] = acc[mf][nf0 + nf][2];
                    T[cl + 1][rl + 8] = acc[mf][nf0 + nf][3];
                }
            }
        }
        __syncthreads();
        int jj = tid >> 2, seg = (tid & 3) * 32;
        size_t base = (size_t)(j0 + s * 32 + jj) * NN + i0 + seg;
#pragma unroll
        for (int q = 0; q < 8; q++)
            *(float4*)&C[base + q * 4] = *(float4*)&T[jj][seg + q * 4];
    }
}

// ================= launch =================
extern "C" void kernel_launch(void* const* d_in, const int* in_sizes, int n_in,
                              void* d_out, int out_size) {
    const float* x        = (const float*)d_in[0];
    const int*   adj_rows = (const int*)d_in[1];
    const int*   adj_cols = (const int*)d_in[2];
    const float* adj_vals = (const float*)d_in[3];
    const float* W1       = (const float*)d_in[4];
    const float* W2       = (const float*)d_in[5];
    const float* W3       = (const float*)d_in[6];
    const float* dense_W  = (const float*)d_in[7];
    const float* dense_b  = (const float*)d_in[8];
    const float* dense1_W = (const float*)d_in[9];
    const float* dense1_b = (const float*)d_in[10];

    float* out = (float*)d_out;
    float* adj = out;
    float* o6  = adj + (size_t)NN * NN;
    float* mu  = o6 + (size_t)NN * O6;
    float* lv  = mu + (size_t)NN * H3D;

    void *p_xw1h, *p_h1h, *p_ah1;
    cudaGetSymbolAddress(&p_xw1h, g_xw1h);
    cudaGetSymbolAddress(&p_h1h, g_h1h);
    cudaGetSymbolAddress(&p_ah1, g_ah1);

    // one-time infra (host objects only; GPU work identical every call)
    static cudaStream_t s_side = nullptr;
    static cudaEvent_t s_fork = nullptr, s_join = nullptr;
    if (!s_side) {
        cudaStreamCreateWithFlags(&s_side, cudaStreamNonBlocking);
        cudaEventCreateWithFlags(&s_fork, cudaEventDisableTiming);
        cudaEventCreateWithFlags(&s_join, cudaEventDisableTiming);
    }

    // fork: CSR chain on side stream, concurrent with pack/xw1 on main
    cudaEventRecord(s_fork, 0);
    cudaStreamWaitEvent(s_side, s_fork, 0);
    hist_kernel<<<NE / 256, 256, 0, s_side>>>(adj_rows);
    scan_kernel<<<1, 1024, 0, s_side>>>();
    scatter_kernel<<<NE / 256, 256, 0, s_side>>>(adj_rows, adj_cols, adj_vals);
    cudaEventRecord(s_join, s_side);

    // main stream: weights + packs + xw1
    wcat_kernel<<<H1D, H2D>>>(W2, W3, dense_W);
    pack_inputs_kernel<<<544, 1024>>>(x, W1);
    xw1_mma_kernel<<<dim3(2, 64), 256>>>((__half*)p_xw1h);

    // join: spmm needs both xw1 and CSR
    cudaStreamWaitEvent(0, s_join, 0);

    spmm_h2h<<<NN / 4, 256>>>((const __half*)p_xw1h, (__half*)p_h1h);
    spmm_h2f<<<NN / 4, 256>>>((const __half*)p_h1h, (float*)p_ah1);

    ml_fused_kernel<<<NN / 128, 256>>>((const float*)p_ah1, dense_b, dense1_W, dense1_b,
                                       mu, lv, o6);

    zzt_kernel<<<dim3(64, 64), 128>>>(adj);
}